// round 5
// baseline (speedup 1.0000x reference)
#include <cuda_runtime.h>
#include <cuda_fp16.h>
#include <cstdint>

#define Bb 4
#define Ss 2048
#define Dd 1024

#define BM 128
#define BN 256
#define BK 64                                  // fp16: 64 * 2B = 128B per row
#define STAGES 3
#define A_BYTES (BM * 128)                     // 16KB
#define B_BYTES (BN * 128)                     // 32KB
#define STAGE_BYTES (A_BYTES + B_BYTES)        // 48KB

// ---------------- device scratch (allocation-free rule) ----------------
__device__ __align__(1024) __half g_x16[Bb * Ss * Dd];
__device__ __align__(1024) __half g_W16[3 * Dd * Dd];
__device__ __align__(1024) __half g_Q16[Bb * Ss * Dd];
__device__ __align__(1024) __half g_K16[Bb * Ss * Dd];
__device__ __align__(1024) __half g_Vt16[Bb * Ss * Dd];
__device__ __align__(1024) float  g_P32[Bb * Ss * Ss];
__device__ __align__(1024) __half g_P16[Bb * Ss * Ss];

// ---------------- helpers ----------------
__device__ __forceinline__ uint32_t smem_u32(const void* p) {
    uint32_t a;
    asm("{ .reg .u64 t; cvta.to.shared.u64 t, %1; cvt.u32.u64 %0, t; }" : "=r"(a) : "l"(p));
    return a;
}
__device__ __forceinline__ void cp16(uint32_t dst, const void* src) {
    asm volatile("cp.async.cg.shared.global [%0], [%1], 16;" :: "r"(dst), "l"(src));
}
__device__ __forceinline__ void cp_commit() {
    asm volatile("cp.async.commit_group;" ::: "memory");
}
__device__ __forceinline__ void cp_wait1() {
    asm volatile("cp.async.wait_group 1;" ::: "memory");
}
__device__ __forceinline__ void ldsm4(uint32_t& r0, uint32_t& r1, uint32_t& r2, uint32_t& r3,
                                      uint32_t addr) {
    asm volatile("ldmatrix.sync.aligned.m8n8.x4.shared.b16 {%0,%1,%2,%3}, [%4];"
                 : "=r"(r0), "=r"(r1), "=r"(r2), "=r"(r3) : "r"(addr));
}
__device__ __forceinline__ void mma_f16(float* c, const uint32_t* a, uint32_t b0, uint32_t b1) {
    asm volatile(
        "mma.sync.aligned.m16n8k16.row.col.f32.f16.f16.f32 "
        "{%0,%1,%2,%3}, {%4,%5,%6,%7}, {%8,%9}, {%0,%1,%2,%3};"
        : "+f"(c[0]), "+f"(c[1]), "+f"(c[2]), "+f"(c[3])
        : "r"(a[0]), "r"(a[1]), "r"(a[2]), "r"(a[3]), "r"(b0), "r"(b1));
}

// ------- fp16 mma.sync GEMM:  C[M,N] = A[M,K] @ B[N,K]^T * alpha (+bias) -------
// BIAS_MODE: 0 = none, 1 = per-column bias, 2 = per-row bias.
template <int BIAS_MODE, bool HALF_OUT>
__global__ void __launch_bounds__(256, 1) hgemm(
    const __half* __restrict__ A, const __half* __restrict__ Bm,
    const float* __restrict__ bias, void* __restrict__ Cv,
    int Ntot, int Ktot, float alpha,
    long long sA, long long sB, long long sC)
{
    extern __shared__ __align__(1024) char smem[];
    const uint32_t sb = smem_u32(smem);

    const int tid = threadIdx.x;
    const int lane = tid & 31;
    const int wid = tid >> 5;
    const int wm = wid & 1;        // 2 warps in M (64 rows each)
    const int wn = wid >> 1;       // 4 warps in N (64 cols each)

    const int rowBase = blockIdx.y * BM;
    const int colBase = blockIdx.x * BN;
    const __half* Ab  = A  + blockIdx.z * sA + (long long)rowBase * Ktot;
    const __half* Bg0 = Bm + blockIdx.z * sB + (long long)colBase * Ktot;

    // loader: rows of 128B; 32 rows per pass
    const int lr = tid >> 3;       // 0..31
    const int lc = tid & 7;        // 0..7

    const int frow = lane & 15;
    const int fkc = lane >> 4;

    float acc[4][8][4];
#pragma unroll
    for (int i = 0; i < 4; i++)
#pragma unroll
        for (int j = 0; j < 8; j++)
#pragma unroll
            for (int q = 0; q < 4; q++) acc[i][j][q] = 0.0f;

    const int kIters = Ktot / BK;

    auto load_stage = [&](int buf, int kt) {
        const uint32_t sbase = sb + buf * STAGE_BYTES;
        const __half* Ag = Ab + kt * BK;
        const __half* Bg = Bg0 + kt * BK;
#pragma unroll
        for (int p = 0; p < 4; p++) {
            const int row = lr + 32 * p;
            const uint32_t off = row * 128 + ((uint32_t)(lc ^ (row & 7)) << 4);
            cp16(sbase + off, Ag + (long long)row * Ktot + lc * 8);
        }
#pragma unroll
        for (int p = 0; p < 8; p++) {
            const int row = lr + 32 * p;
            const uint32_t off = row * 128 + ((uint32_t)(lc ^ (row & 7)) << 4);
            cp16(sbase + A_BYTES + off, Bg + (long long)row * Ktot + lc * 8);
        }
    };

#pragma unroll
    for (int s = 0; s < STAGES - 1; s++) {
        if (s < kIters) load_stage(s, s);
        cp_commit();
    }

    int arow[4], brow[4];
#pragma unroll
    for (int mt = 0; mt < 4; mt++) arow[mt] = wm * 64 + mt * 16 + frow;
#pragma unroll
    for (int p = 0; p < 4; p++) brow[p] = wn * 64 + p * 16 + frow;

    for (int it = 0; it < kIters; it++) {
        cp_wait1();
        __syncthreads();

        const int nx = it + STAGES - 1;
        if (nx < kIters) load_stage(nx % STAGES, nx);
        cp_commit();

        const uint32_t As = sb + (it % STAGES) * STAGE_BYTES;
        const uint32_t Bs = As + A_BYTES;

#pragma unroll
        for (int ks = 0; ks < 4; ks++) {            // 4 x k16 steps = K64
            const int chunk = 2 * ks + fkc;
            uint32_t a[4][4];
#pragma unroll
            for (int mt = 0; mt < 4; mt++) {
                const uint32_t ad = As + arow[mt] * 128 +
                                    ((uint32_t)(chunk ^ (arow[mt] & 7)) << 4);
                ldsm4(a[mt][0], a[mt][1], a[mt][2], a[mt][3], ad);
            }
            uint32_t b[4][4];
#pragma unroll
            for (int p = 0; p < 4; p++) {
                const uint32_t bd = Bs + brow[p] * 128 +
                                    ((uint32_t)(chunk ^ (brow[p] & 7)) << 4);
                ldsm4(b[p][0], b[p][1], b[p][2], b[p][3], bd);
            }
#pragma unroll
            for (int mt = 0; mt < 4; mt++)
#pragma unroll
                for (int nt = 0; nt < 8; nt++) {
                    const int p = nt >> 1, o = nt & 1;
                    mma_f16(acc[mt][nt], a[mt], b[p][o], b[p][2 + o]);
                }
        }
        __syncthreads();
    }

    // ---- epilogue ----
    const int g = lane >> 2;
    const int cpair = (lane & 3) * 2;
#pragma unroll
    for (int mt = 0; mt < 4; mt++) {
        const long long r0 = rowBase + wm * 64 + mt * 16 + g;
        const long long r1 = r0 + 8;
        float rb0 = 0.f, rb1 = 0.f;
        if (BIAS_MODE == 2) { rb0 = bias[r0]; rb1 = bias[r1]; }
#pragma unroll
        for (int nt = 0; nt < 8; nt++) {
            const int col = colBase + wn * 64 + nt * 8 + cpair;
            float bx = 0.f, by = 0.f;
            if (BIAS_MODE == 1) { bx = bias[col]; by = bias[col + 1]; }
            float2 v0, v1;
            v0.x = acc[mt][nt][0] * alpha + bx + rb0;
            v0.y = acc[mt][nt][1] * alpha + by + rb0;
            v1.x = acc[mt][nt][2] * alpha + bx + rb1;
            v1.y = acc[mt][nt][3] * alpha + by + rb1;
            if (HALF_OUT) {
                __half* Cb = (__half*)Cv + blockIdx.z * sC;
                *reinterpret_cast<__half2*>(Cb + r0 * Ntot + col) = __floats2half2_rn(v0.x, v0.y);
                *reinterpret_cast<__half2*>(Cb + r1 * Ntot + col) = __floats2half2_rn(v1.x, v1.y);
            } else {
                float* Cb = (float*)Cv + blockIdx.z * sC;
                *reinterpret_cast<float2*>(Cb + r0 * Ntot + col) = v0;
                *reinterpret_cast<float2*>(Cb + r1 * Ntot + col) = v1;
            }
        }
    }
}

// ---------------- fp32 -> fp16 converts ----------------
__global__ void cvt_half_kernel(const float* __restrict__ in, __half* __restrict__ out, int n4)
{
    int i = blockIdx.x * blockDim.x + threadIdx.x;
    if (i >= n4) return;
    const float4 v = reinterpret_cast<const float4*>(in)[i];
    __half2* o = reinterpret_cast<__half2*>(out);
    o[2 * i]     = __floats2half2_rn(v.x, v.y);
    o[2 * i + 1] = __floats2half2_rn(v.z, v.w);
}

__global__ void cvt_w_kernel(const float* __restrict__ w0, const float* __restrict__ w1,
                             const float* __restrict__ w2, __half* __restrict__ out)
{
    const int n4 = Dd * Dd / 4;
    int i = blockIdx.x * blockDim.x + threadIdx.x;
    if (i >= n4) return;
    const float* in = (blockIdx.y == 0) ? w0 : (blockIdx.y == 1) ? w1 : w2;
    const float4 v = reinterpret_cast<const float4*>(in)[i];
    __half2* o = reinterpret_cast<__half2*>(out + (long long)blockIdx.y * Dd * Dd);
    o[2 * i]     = __floats2half2_rn(v.x, v.y);
    o[2 * i + 1] = __floats2half2_rn(v.z, v.w);
}

// ------- row softmax over S=2048: reads fp32 scores, writes fp16 P -------
__global__ void __launch_bounds__(256) softmax_kernel(const float* __restrict__ S32,
                                                      __half* __restrict__ P16)
{
    const float* row = S32 + (long long)blockIdx.x * Ss;
    __half* orow = P16 + (long long)blockIdx.x * Ss;
    const int tid = threadIdx.x;
    const int w = tid >> 5, l = tid & 31;

    float v[8];
    float m = -1e30f;
#pragma unroll
    for (int i = 0; i < 8; i++) { v[i] = row[tid + i * 256]; m = fmaxf(m, v[i]); }
#pragma unroll
    for (int o = 16; o > 0; o >>= 1) m = fmaxf(m, __shfl_xor_sync(0xFFFFFFFFu, m, o));

    __shared__ float smax[8], ssum[8];
    if (l == 0) smax[w] = m;
    __syncthreads();
    m = smax[0];
#pragma unroll
    for (int i = 1; i < 8; i++) m = fmaxf(m, smax[i]);

    float s = 0.0f;
#pragma unroll
    for (int i = 0; i < 8; i++) { v[i] = __expf(v[i] - m); s += v[i]; }
#pragma unroll
    for (int o = 16; o > 0; o >>= 1) s += __shfl_xor_sync(0xFFFFFFFFu, s, o);
    if (l == 0) ssum[w] = s;
    __syncthreads();
    float tot = 0.0f;
#pragma unroll
    for (int i = 0; i < 8; i++) tot += ssum[i];
    const float inv = 1.0f / tot;
#pragma unroll
    for (int i = 0; i < 8; i++) orow[tid + i * 256] = __float2half_rn(v[i] * inv);
}

// ---------------- host ----------------
extern "C" void kernel_launch(void* const* d_in, const int* in_sizes, int n_in,
                              void* d_out, int out_size)
{
    const float* x  = (const float*)d_in[0];
    const float* Wq = (const float*)d_in[1];
    const float* bq = (const float*)d_in[2];
    const float* Wk = (const float*)d_in[3];
    const float* bk = (const float*)d_in[4];
    const float* Wv = (const float*)d_in[5];
    const float* bv = (const float*)d_in[6];
    float* out = (float*)d_out;

    __half *x16, *W16, *Q16, *K16, *Vt16, *P16;
    float* P32;
    cudaGetSymbolAddress((void**)&x16, g_x16);
    cudaGetSymbolAddress((void**)&W16, g_W16);
    cudaGetSymbolAddress((void**)&Q16, g_Q16);
    cudaGetSymbolAddress((void**)&K16, g_K16);
    cudaGetSymbolAddress((void**)&Vt16, g_Vt16);
    cudaGetSymbolAddress((void**)&P32, g_P32);
    cudaGetSymbolAddress((void**)&P16, g_P16);

    const int smemBytes = STAGES * STAGE_BYTES;   // 144KB
    cudaFuncSetAttribute(hgemm<1, true>, cudaFuncAttributeMaxDynamicSharedMemorySize, smemBytes);
    cudaFuncSetAttribute(hgemm<2, true>, cudaFuncAttributeMaxDynamicSharedMemorySize, smemBytes);
    cudaFuncSetAttribute(hgemm<0, false>, cudaFuncAttributeMaxDynamicSharedMemorySize, smemBytes);

    // 0) convert inputs to fp16 (RN)
    cvt_half_kernel<<<(Bb * Ss * Dd / 4 + 255) / 256, 256>>>(x, x16, Bb * Ss * Dd / 4);
    cvt_w_kernel<<<dim3((Dd * Dd / 4 + 255) / 256, 3), 256>>>(Wq, Wk, Wv, W16);

    const long long SD = (long long)Ss * Dd;
    const long long SS2 = (long long)Ss * Ss;

    // 1) Q/K projections: [8192,1024] = x16 @ W^T + b (per-col bias)
    const dim3 g1(Dd / BN, (Bb * Ss) / BM, 1);
    hgemm<1, true><<<g1, 256, smemBytes>>>(x16, W16 + 0 * Dd * Dd, bq, Q16, Dd, Dd, 1.0f, 0, 0, 0);
    hgemm<1, true><<<g1, 256, smemBytes>>>(x16, W16 + 1 * Dd * Dd, bk, K16, Dd, Dd, 1.0f, 0, 0, 0);

    // 1b) V projection, transposed output: Vt[b][e][s] = Wv[e,:] . x[b][s,:] + bv[e]
    //     A = Wv (M=e), B = x16 per batch (N=s), per-row bias.
    const dim3 gv(Ss / BN, Dd / BM, Bb);
    hgemm<2, true><<<gv, 256, smemBytes>>>(W16 + 2 * Dd * Dd, x16, bv, Vt16, Ss, Dd, 1.0f, 0, SD, SD);

    // 2) scores = Q @ K^T / 32 -> fp32 (protect softmax numerics)
    const dim3 g2(Ss / BN, Ss / BM, Bb);
    hgemm<0, false><<<g2, 256, smemBytes>>>(Q16, K16, nullptr, P32, Ss, Dd, 0.03125f, SD, SD, SS2);

    // 3) softmax fp32 -> fp16 P
    softmax_kernel<<<Bb * Ss, 256>>>(P32, P16);

    // 4) out = P16 @ Vt16^T -> fp32
    const dim3 g3(Dd / BN, Ss / BM, Bb);
    hgemm<0, false><<<g3, 256, smemBytes>>>(P16, Vt16, nullptr, out, Dd, Ss, 1.0f, SS2, SD, SD);
}

// round 6
// speedup vs baseline: 1.1282x; 1.1282x over previous
#include <cuda_runtime.h>
#include <cuda_fp16.h>
#include <cstdint>

#define Bb 4
#define Ss 2048
#define Dd 1024

#define BM 128
#define BN 128
#define BK 64                                  // fp16: 64 * 2B = 128B per row
#define STAGES 3
#define A_BYTES (BM * 128)                     // 16KB
#define STAGE_BYTES (2 * A_BYTES)              // 32KB

// ---------------- device scratch (allocation-free rule) ----------------
__device__ __align__(1024) __half g_x16[Bb * Ss * Dd];
__device__ __align__(1024) __half g_W16[3 * Dd * Dd];
__device__ __align__(1024) __half g_Q16[Bb * Ss * Dd];
__device__ __align__(1024) __half g_K16[Bb * Ss * Dd];
__device__ __align__(1024) __half g_Vt16[Bb * Ss * Dd];
__device__ __align__(1024) float  g_P32[Bb * Ss * Ss];
__device__ __align__(1024) __half g_P16[Bb * Ss * Ss];

// ---------------- helpers ----------------
__device__ __forceinline__ uint32_t smem_u32(const void* p) {
    uint32_t a;
    asm("{ .reg .u64 t; cvta.to.shared.u64 t, %1; cvt.u32.u64 %0, t; }" : "=r"(a) : "l"(p));
    return a;
}
__device__ __forceinline__ void cp16(uint32_t dst, const void* src) {
    asm volatile("cp.async.cg.shared.global [%0], [%1], 16;" :: "r"(dst), "l"(src));
}
__device__ __forceinline__ void cp_commit() {
    asm volatile("cp.async.commit_group;" ::: "memory");
}
__device__ __forceinline__ void cp_wait1() {
    asm volatile("cp.async.wait_group 1;" ::: "memory");
}
__device__ __forceinline__ void ldsm4(uint32_t& r0, uint32_t& r1, uint32_t& r2, uint32_t& r3,
                                      uint32_t addr) {
    asm volatile("ldmatrix.sync.aligned.m8n8.x4.shared.b16 {%0,%1,%2,%3}, [%4];"
                 : "=r"(r0), "=r"(r1), "=r"(r2), "=r"(r3) : "r"(addr));
}
__device__ __forceinline__ void mma_f16(float* c, const uint32_t* a, uint32_t b0, uint32_t b1) {
    asm volatile(
        "mma.sync.aligned.m16n8k16.row.col.f32.f16.f16.f32 "
        "{%0,%1,%2,%3}, {%4,%5,%6,%7}, {%8,%9}, {%0,%1,%2,%3};"
        : "+f"(c[0]), "+f"(c[1]), "+f"(c[2]), "+f"(c[3])
        : "r"(a[0]), "r"(a[1]), "r"(a[2]), "r"(a[3]), "r"(b0), "r"(b1));
}

// ------- fp16 mma.sync GEMM:  C[M,N] = A[M,K] @ B[N,K]^T * alpha (+bias) -------
// BIAS_MODE: 0 = none, 1 = per-column bias, 2 = per-row bias.
// PAIRED: blockIdx.z in {0,1} selects (Bm, bias, C) pair; A shared; no batching.
template <int BIAS_MODE, bool HALF_OUT, bool PAIRED>
__global__ void __launch_bounds__(256, 2) hgemm(
    const __half* __restrict__ A, const __half* __restrict__ Bm,
    const float* __restrict__ bias, const float* __restrict__ bias2,
    void* __restrict__ Cv, void* __restrict__ Cv2,
    int Ntot, int Ktot, float alpha,
    long long sA, long long sB, long long sC)
{
    extern __shared__ __align__(1024) char smem[];
    const uint32_t sb = smem_u32(smem);

    const int tid = threadIdx.x;
    const int lane = tid & 31;
    const int wid = tid >> 5;
    const int wm = wid & 1;        // 2 warps in M (64 rows each)
    const int wn = wid >> 1;       // 4 warps in N (32 cols each)

    int bz;
    if (PAIRED) {
        bz = 0;
        if (blockIdx.z) { Bm += sB; bias = bias2; Cv = Cv2; }
    } else {
        bz = blockIdx.z;
    }

    const int rowBase = blockIdx.y * BM;
    const int colBase = blockIdx.x * BN;
    const __half* Ab  = A  + (PAIRED ? 0 : bz * sA) + (long long)rowBase * Ktot;
    const __half* Bg0 = Bm + (PAIRED ? 0 : bz * sB) + (long long)colBase * Ktot;

    // loader: rows of 128B; 32 rows per pass, 4 passes per operand tile
    const int lr = tid >> 3;       // 0..31
    const int lc = tid & 7;        // 0..7

    const int frow = lane & 15;
    const int fkc = lane >> 4;

    float acc[4][4][4];
#pragma unroll
    for (int i = 0; i < 4; i++)
#pragma unroll
        for (int j = 0; j < 4; j++)
#pragma unroll
            for (int q = 0; q < 4; q++) acc[i][j][q] = 0.0f;

    const int kIters = Ktot / BK;

    auto load_stage = [&](int buf, int kt) {
        const uint32_t sbase = sb + buf * STAGE_BYTES;
        const __half* Ag = Ab + kt * BK;
        const __half* Bg = Bg0 + kt * BK;
#pragma unroll
        for (int p = 0; p < 4; p++) {
            const int row = lr + 32 * p;
            const uint32_t off = row * 128 + ((uint32_t)(lc ^ (row & 7)) << 4);
            cp16(sbase + off, Ag + (long long)row * Ktot + lc * 8);
            cp16(sbase + A_BYTES + off, Bg + (long long)row * Ktot + lc * 8);
        }
    };

#pragma unroll
    for (int s = 0; s < STAGES - 1; s++) {
        if (s < kIters) load_stage(s, s);
        cp_commit();
    }

    int arow[4], brow[2];
#pragma unroll
    for (int mt = 0; mt < 4; mt++) arow[mt] = wm * 64 + mt * 16 + frow;
#pragma unroll
    for (int p = 0; p < 2; p++) brow[p] = wn * 32 + p * 16 + frow;

    for (int it = 0; it < kIters; it++) {
        cp_wait1();
        // Single barrier per iter: once all warps arrive here, every warp has
        // finished iter it-1's ldsm reads of buffer (it-1)%3 == (it+2)%3, so
        // issuing cp.async writes to (it+2)%3 below is safe.
        __syncthreads();

        const int nx = it + STAGES - 1;
        if (nx < kIters) load_stage(nx % STAGES, nx);
        cp_commit();

        const uint32_t As = sb + (it % STAGES) * STAGE_BYTES;
        const uint32_t Bs = As + A_BYTES;

#pragma unroll
        for (int ks = 0; ks < 4; ks++) {            // 4 x k16 steps = K64
            const int chunk = 2 * ks + fkc;
            uint32_t a[4][4];
#pragma unroll
            for (int mt = 0; mt < 4; mt++) {
                const uint32_t ad = As + arow[mt] * 128 +
                                    ((uint32_t)(chunk ^ (arow[mt] & 7)) << 4);
                ldsm4(a[mt][0], a[mt][1], a[mt][2], a[mt][3], ad);
            }
            uint32_t b[2][4];
#pragma unroll
            for (int p = 0; p < 2; p++) {
                const uint32_t bd = Bs + brow[p] * 128 +
                                    ((uint32_t)(chunk ^ (brow[p] & 7)) << 4);
                ldsm4(b[p][0], b[p][1], b[p][2], b[p][3], bd);
            }
#pragma unroll
            for (int mt = 0; mt < 4; mt++)
#pragma unroll
                for (int nt = 0; nt < 4; nt++) {
                    const int p = nt >> 1, o = nt & 1;
                    mma_f16(acc[mt][nt], a[mt], b[p][o], b[p][2 + o]);
                }
        }
    }

    // ---- epilogue ----
    const int g = lane >> 2;
    const int cpair = (lane & 3) * 2;
#pragma unroll
    for (int mt = 0; mt < 4; mt++) {
        const long long r0 = rowBase + wm * 64 + mt * 16 + g;
        const long long r1 = r0 + 8;
        float rb0 = 0.f, rb1 = 0.f;
        if (BIAS_MODE == 2) { rb0 = bias[r0]; rb1 = bias[r1]; }
#pragma unroll
        for (int nt = 0; nt < 4; nt++) {
            const int col = colBase + wn * 32 + nt * 8 + cpair;
            float bx = 0.f, by = 0.f;
            if (BIAS_MODE == 1) { bx = bias[col]; by = bias[col + 1]; }
            float2 v0, v1;
            v0.x = acc[mt][nt][0] * alpha + bx + rb0;
            v0.y = acc[mt][nt][1] * alpha + by + rb0;
            v1.x = acc[mt][nt][2] * alpha + bx + rb1;
            v1.y = acc[mt][nt][3] * alpha + by + rb1;
            if (HALF_OUT) {
                __half* Cb = (__half*)Cv + bz * sC;
                *reinterpret_cast<__half2*>(Cb + r0 * Ntot + col) = __floats2half2_rn(v0.x, v0.y);
                *reinterpret_cast<__half2*>(Cb + r1 * Ntot + col) = __floats2half2_rn(v1.x, v1.y);
            } else {
                float* Cb = (float*)Cv + bz * sC;
                *reinterpret_cast<float2*>(Cb + r0 * Ntot + col) = v0;
                *reinterpret_cast<float2*>(Cb + r1 * Ntot + col) = v1;
            }
        }
    }
}

// ---------------- fp32 -> fp16 converts ----------------
__global__ void cvt_half_kernel(const float* __restrict__ in, __half* __restrict__ out, int n4)
{
    int i = blockIdx.x * blockDim.x + threadIdx.x;
    if (i >= n4) return;
    const float4 v = reinterpret_cast<const float4*>(in)[i];
    __half2* o = reinterpret_cast<__half2*>(out);
    o[2 * i]     = __floats2half2_rn(v.x, v.y);
    o[2 * i + 1] = __floats2half2_rn(v.z, v.w);
}

__global__ void cvt_w_kernel(const float* __restrict__ w0, const float* __restrict__ w1,
                             const float* __restrict__ w2, __half* __restrict__ out)
{
    const int n4 = Dd * Dd / 4;
    int i = blockIdx.x * blockDim.x + threadIdx.x;
    if (i >= n4) return;
    const float* in = (blockIdx.y == 0) ? w0 : (blockIdx.y == 1) ? w1 : w2;
    const float4 v = reinterpret_cast<const float4*>(in)[i];
    __half2* o = reinterpret_cast<__half2*>(out + (long long)blockIdx.y * Dd * Dd);
    o[2 * i]     = __floats2half2_rn(v.x, v.y);
    o[2 * i + 1] = __floats2half2_rn(v.z, v.w);
}

// ------- row softmax over S=2048: reads fp32 scores, writes fp16 P -------
__global__ void __launch_bounds__(256) softmax_kernel(const float* __restrict__ S32,
                                                      __half* __restrict__ P16)
{
    const float* row = S32 + (long long)blockIdx.x * Ss;
    __half* orow = P16 + (long long)blockIdx.x * Ss;
    const int tid = threadIdx.x;
    const int w = tid >> 5, l = tid & 31;

    float v[8];
    float m = -1e30f;
#pragma unroll
    for (int i = 0; i < 8; i++) { v[i] = row[tid + i * 256]; m = fmaxf(m, v[i]); }
#pragma unroll
    for (int o = 16; o > 0; o >>= 1) m = fmaxf(m, __shfl_xor_sync(0xFFFFFFFFu, m, o));

    __shared__ float smax[8], ssum[8];
    if (l == 0) smax[w] = m;
    __syncthreads();
    m = smax[0];
#pragma unroll
    for (int i = 1; i < 8; i++) m = fmaxf(m, smax[i]);

    float s = 0.0f;
#pragma unroll
    for (int i = 0; i < 8; i++) { v[i] = __expf(v[i] - m); s += v[i]; }
#pragma unroll
    for (int o = 16; o > 0; o >>= 1) s += __shfl_xor_sync(0xFFFFFFFFu, s, o);
    if (l == 0) ssum[w] = s;
    __syncthreads();
    float tot = 0.0f;
#pragma unroll
    for (int i = 0; i < 8; i++) tot += ssum[i];
    const float inv = 1.0f / tot;
#pragma unroll
    for (int i = 0; i < 8; i++) orow[tid + i * 256] = __float2half_rn(v[i] * inv);
}

// ---------------- host ----------------
extern "C" void kernel_launch(void* const* d_in, const int* in_sizes, int n_in,
                              void* d_out, int out_size)
{
    const float* x  = (const float*)d_in[0];
    const float* Wq = (const float*)d_in[1];
    const float* bq = (const float*)d_in[2];
    const float* Wk = (const float*)d_in[3];
    const float* bk = (const float*)d_in[4];
    const float* Wv = (const float*)d_in[5];
    const float* bv = (const float*)d_in[6];
    float* out = (float*)d_out;

    __half *x16, *W16, *Q16, *K16, *Vt16, *P16;
    float* P32;
    cudaGetSymbolAddress((void**)&x16, g_x16);
    cudaGetSymbolAddress((void**)&W16, g_W16);
    cudaGetSymbolAddress((void**)&Q16, g_Q16);
    cudaGetSymbolAddress((void**)&K16, g_K16);
    cudaGetSymbolAddress((void**)&Vt16, g_Vt16);
    cudaGetSymbolAddress((void**)&P32, g_P32);
    cudaGetSymbolAddress((void**)&P16, g_P16);

    const int smemBytes = STAGES * STAGE_BYTES;   // 96KB
    cudaFuncSetAttribute((const void*)hgemm<1, true, true>,
                         cudaFuncAttributeMaxDynamicSharedMemorySize, smemBytes);
    cudaFuncSetAttribute((const void*)hgemm<2, true, false>,
                         cudaFuncAttributeMaxDynamicSharedMemorySize, smemBytes);
    cudaFuncSetAttribute((const void*)hgemm<0, false, false>,
                         cudaFuncAttributeMaxDynamicSharedMemorySize, smemBytes);

    // 0) convert inputs to fp16 (RN)
    cvt_half_kernel<<<(Bb * Ss * Dd / 4 + 255) / 256, 256>>>(x, x16, Bb * Ss * Dd / 4);
    cvt_w_kernel<<<dim3((Dd * Dd / 4 + 255) / 256, 3), 256>>>(Wq, Wk, Wv, W16);

    const long long SD = (long long)Ss * Dd;
    const long long SS2 = (long long)Ss * Ss;
    const long long DD = (long long)Dd * Dd;

    // 1) Q and K projections, one launch (z selects W/bias/output)
    const dim3 gqk(Dd / BN, (Bb * Ss) / BM, 2);
    hgemm<1, true, true><<<gqk, 256, smemBytes>>>(
        x16, W16, bq, bk, Q16, K16, Dd, Dd, 1.0f, 0, DD, 0);

    // 1b) V projection, transposed output: Vt[b][e][s] = Wv[e,:] . x[b][s,:] + bv[e]
    const dim3 gv(Ss / BN, Dd / BM, Bb);
    hgemm<2, true, false><<<gv, 256, smemBytes>>>(
        W16 + 2 * DD, x16, bv, nullptr, Vt16, nullptr, Ss, Dd, 1.0f, 0, SD, SD);

    // 2) scores = Q @ K^T / 32 -> fp32 (protect softmax numerics)
    const dim3 g2(Ss / BN, Ss / BM, Bb);
    hgemm<0, false, false><<<g2, 256, smemBytes>>>(
        Q16, K16, nullptr, nullptr, P32, nullptr, Ss, Dd, 0.03125f, SD, SD, SS2);

    // 3) softmax fp32 -> fp16 P
    softmax_kernel<<<Bb * Ss, 256>>>(P32, P16);

    // 4) out = P16 @ Vt16^T -> fp32
    const dim3 g3(Dd / BN, Ss / BM, Bb);
    hgemm<0, false, false><<<g3, 256, smemBytes>>>(
        P16, Vt16, nullptr, nullptr, out, nullptr, Dd, Ss, 1.0f, SS2, SD, SD);
}

// round 7
// speedup vs baseline: 1.1770x; 1.0432x over previous
#include <cuda_runtime.h>
#include <cuda_fp16.h>
#include <cstdint>

#define Bb 4
#define Ss 2048
#define Dd 1024

#define BM 128
#define BN 128
#define BK 64                                  // fp16: 64 * 2B = 128B per row
#define A_BYTES (BM * 128)                     // 16KB
#define STAGE_BYTES (2 * A_BYTES)              // 32KB
#define SMEM_BYTES (3 * STAGE_BYTES)           // 96KB, 3 stages

// ---------------- device scratch (allocation-free rule) ----------------
__device__ __align__(1024) __half g_x16[Bb * Ss * Dd];
__device__ __align__(1024) __half g_W16[3 * Dd * Dd];
__device__ __align__(1024) __half g_Q16[Bb * Ss * Dd];
__device__ __align__(1024) __half g_K16[Bb * Ss * Dd];
__device__ __align__(1024) __half g_Vt16[Bb * Ss * Dd];
__device__ __align__(1024) float  g_P32[Bb * Ss * Ss];
__device__ __align__(1024) __half g_P16[Bb * Ss * Ss];

// ---------------- helpers ----------------
__device__ __forceinline__ uint32_t smem_u32(const void* p) {
    uint32_t a;
    asm("{ .reg .u64 t; cvta.to.shared.u64 t, %1; cvt.u32.u64 %0, t; }" : "=r"(a) : "l"(p));
    return a;
}
__device__ __forceinline__ void cp16(uint32_t dst, const void* src) {
    asm volatile("cp.async.cg.shared.global [%0], [%1], 16;" :: "r"(dst), "l"(src));
}
__device__ __forceinline__ void cp_commit() {
    asm volatile("cp.async.commit_group;" ::: "memory");
}
__device__ __forceinline__ void cp_wait1() {
    asm volatile("cp.async.wait_group 1;" ::: "memory");
}
__device__ __forceinline__ void ldsm4(uint32_t& r0, uint32_t& r1, uint32_t& r2, uint32_t& r3,
                                      uint32_t addr) {
    asm volatile("ldmatrix.sync.aligned.m8n8.x4.shared.b16 {%0,%1,%2,%3}, [%4];"
                 : "=r"(r0), "=r"(r1), "=r"(r2), "=r"(r3) : "r"(addr));
}
__device__ __forceinline__ void mma_f16(float* c, const uint32_t* a, uint32_t b0, uint32_t b1) {
    asm volatile(
        "mma.sync.aligned.m16n8k16.row.col.f32.f16.f16.f32 "
        "{%0,%1,%2,%3}, {%4,%5,%6,%7}, {%8,%9}, {%0,%1,%2,%3};"
        : "+f"(c[0]), "+f"(c[1]), "+f"(c[2]), "+f"(c[3])
        : "r"(a[0]), "r"(a[1]), "r"(a[2]), "r"(a[3]), "r"(b0), "r"(b1));
}

// ======= shared fp16 mma.sync GEMM body: C[M,N] = A @ B^T * alpha (+bias) =======
// Ab  = A base with rowBase*Ktot applied, Bg0 = B base with colBase*Ktot applied.
// biasMode: 0 none, 1 per-column, 2 per-row. HALF_OUT selects fp16/fp32 C.
template <bool HALF_OUT>
__device__ __forceinline__ void gemm_body(
    const __half* __restrict__ Ab, const __half* __restrict__ Bg0,
    const float* __restrict__ bias, int biasMode,
    void* __restrict__ Cv, int Ntot, int Ktot, float alpha,
    int rowBase, int colBase, uint32_t sb)
{
    const int tid = threadIdx.x;
    const int lane = tid & 31;
    const int wid = tid >> 5;
    const int wm = wid & 1;        // 2 warps in M (64 rows each)
    const int wn = wid >> 1;       // 4 warps in N (32 cols each)

    // -------- loader precompute: offsets are per-thread constants --------
    const int lr = tid >> 3;       // 0..31
    const int lc = tid & 7;        // 0..7
    uint32_t soff[4];
    const __half* pA[4];
    const __half* pB[4];
#pragma unroll
    for (int p = 0; p < 4; p++) {
        const int row = lr + 32 * p;
        soff[p] = row * 128 + ((uint32_t)(lc ^ (row & 7)) << 4);
        pA[p] = Ab + (long long)row * Ktot + lc * 8;
        pB[p] = Bg0 + (long long)row * Ktot + lc * 8;
    }

    const int frow = lane & 15;
    const int fkc = lane >> 4;

    float acc[4][4][4];
#pragma unroll
    for (int i = 0; i < 4; i++)
#pragma unroll
        for (int j = 0; j < 4; j++)
#pragma unroll
            for (int q = 0; q < 4; q++) acc[i][j][q] = 0.0f;

    const int kIters = Ktot / BK;

    // Issues loads for the NEXT sequential k-chunk; pointers self-advance.
    auto load_stage = [&](int buf) {
        const uint32_t sbase = sb + buf * STAGE_BYTES;
#pragma unroll
        for (int p = 0; p < 4; p++) {
            cp16(sbase + soff[p], pA[p]);
            cp16(sbase + A_BYTES + soff[p], pB[p]);
            pA[p] += BK;
            pB[p] += BK;
        }
    };

    // prologue: stages 0 and 1 (kIters >= 2 always here)
    load_stage(0); cp_commit();
    load_stage(1); cp_commit();

    int arow[4], brow[2];
#pragma unroll
    for (int mt = 0; mt < 4; mt++) arow[mt] = wm * 64 + mt * 16 + frow;
#pragma unroll
    for (int p = 0; p < 2; p++) brow[p] = wn * 32 + p * 16 + frow;

    int nbuf = 2;   // next stage buffer to fill
    int cbuf = 0;   // stage buffer to consume
    for (int it = 0; it < kIters; it++) {
        cp_wait1();
        // Single barrier: all warps done reading buffer (it-1)%3 == nbuf before refill.
        __syncthreads();

        if (it + 2 < kIters) load_stage(nbuf);
        cp_commit();
        nbuf = (nbuf + 1 == 3) ? 0 : nbuf + 1;

        const uint32_t As = sb + cbuf * STAGE_BYTES;
        const uint32_t Bs = As + A_BYTES;
        cbuf = (cbuf + 1 == 3) ? 0 : cbuf + 1;

#pragma unroll
        for (int ks = 0; ks < 4; ks++) {            // 4 x k16 steps = K64
            const int chunk = 2 * ks + fkc;
            uint32_t a[4][4];
#pragma unroll
            for (int mt = 0; mt < 4; mt++) {
                const uint32_t ad = As + arow[mt] * 128 +
                                    ((uint32_t)(chunk ^ (arow[mt] & 7)) << 4);
                ldsm4(a[mt][0], a[mt][1], a[mt][2], a[mt][3], ad);
            }
            uint32_t b[2][4];
#pragma unroll
            for (int p = 0; p < 2; p++) {
                const uint32_t bd = Bs + brow[p] * 128 +
                                    ((uint32_t)(chunk ^ (brow[p] & 7)) << 4);
                ldsm4(b[p][0], b[p][1], b[p][2], b[p][3], bd);
            }
#pragma unroll
            for (int mt = 0; mt < 4; mt++)
#pragma unroll
                for (int nt = 0; nt < 4; nt++) {
                    const int p = nt >> 1, o = nt & 1;
                    mma_f16(acc[mt][nt], a[mt], b[p][o], b[p][2 + o]);
                }
        }
    }

    // ---- epilogue ----
    const int g = lane >> 2;
    const int cpair = (lane & 3) * 2;
#pragma unroll
    for (int mt = 0; mt < 4; mt++) {
        const long long r0 = rowBase + wm * 64 + mt * 16 + g;
        const long long r1 = r0 + 8;
        float rb0 = 0.f, rb1 = 0.f;
        if (biasMode == 2) { rb0 = bias[r0]; rb1 = bias[r1]; }
#pragma unroll
        for (int nt = 0; nt < 4; nt++) {
            const int col = colBase + wn * 32 + nt * 8 + cpair;
            float bx = 0.f, by = 0.f;
            if (biasMode == 1) { bx = bias[col]; by = bias[col + 1]; }
            float2 v0, v1;
            v0.x = acc[mt][nt][0] * alpha + bx + rb0;
            v0.y = acc[mt][nt][1] * alpha + by + rb0;
            v1.x = acc[mt][nt][2] * alpha + bx + rb1;
            v1.y = acc[mt][nt][3] * alpha + by + rb1;
            if (HALF_OUT) {
                __half* Cb = (__half*)Cv;
                *reinterpret_cast<__half2*>(Cb + r0 * Ntot + col) = __floats2half2_rn(v0.x, v0.y);
                *reinterpret_cast<__half2*>(Cb + r1 * Ntot + col) = __floats2half2_rn(v1.x, v1.y);
            } else {
                float* Cb = (float*)Cv;
                *reinterpret_cast<float2*>(Cb + r0 * Ntot + col) = v0;
                *reinterpret_cast<float2*>(Cb + r1 * Ntot + col) = v1;
            }
        }
    }
}

// ======= merged QKV projection: 1536 linear CTAs =======
// CTA 0..1023:  Q/K proj  (z = cta>>9: 0=Q, 1=K), tile x = Dd/BN = 8, y = 64.
// CTA 1024..1535: Vt proj (Vt[b][e][s] = Wv[e,:].x[b][s,:] + bv[e]), x = 16, y = 8, 4 batches.
__global__ void __launch_bounds__(256, 2) proj_kernel(
    const __half* __restrict__ x16, const __half* __restrict__ W16,
    const float* __restrict__ bq, const float* __restrict__ bk, const float* __restrict__ bv,
    __half* __restrict__ Q16, __half* __restrict__ K16, __half* __restrict__ Vt16)
{
    extern __shared__ __align__(1024) char smem[];
    const uint32_t sb = smem_u32(smem);
    const long long SD = (long long)Ss * Dd;
    const long long DD = (long long)Dd * Dd;

    const int cta = blockIdx.x;
    if (cta < 1024) {
        const int z = cta >> 9;
        const int rem = cta & 511;
        const int y = rem >> 3, x = rem & 7;
        gemm_body<true>(x16 + (long long)y * BM * Dd,
                        W16 + z * DD + (long long)x * BN * Dd,
                        z ? bk : bq, 1,
                        z ? K16 : Q16, Dd, Dd, 1.0f, y * BM, x * BN, sb);
    } else {
        const int i = cta - 1024;
        const int bz = i >> 7;
        const int rem = i & 127;
        const int y = rem >> 4, x = rem & 15;
        gemm_body<true>(W16 + 2 * DD + (long long)y * BM * Dd,
                        x16 + bz * SD + (long long)x * BN * Dd,
                        bv, 2,
                        Vt16 + bz * SD, Ss, Dd, 1.0f, y * BM, x * BN, sb);
    }
}

// ======= batched GEMM (scores / PV), fp32 out, no bias =======
__global__ void __launch_bounds__(256, 2) bgemm_kernel(
    const __half* __restrict__ A, const __half* __restrict__ Bm,
    float* __restrict__ C, int Ntot, int Ktot, float alpha,
    long long sA, long long sB, long long sC)
{
    extern __shared__ __align__(1024) char smem[];
    const uint32_t sb = smem_u32(smem);
    const int bz = blockIdx.z;
    gemm_body<false>(A + bz * sA + (long long)blockIdx.y * BM * Ktot,
                     Bm + bz * sB + (long long)blockIdx.x * BN * Ktot,
                     nullptr, 0,
                     C + bz * sC, Ntot, Ktot, alpha,
                     blockIdx.y * BM, blockIdx.x * BN, sb);
}

// ---------------- merged fp32 -> fp16 convert (x and 3 weights) ----------------
__global__ void cvt_all_kernel(const float* __restrict__ x,
                               const float* __restrict__ wq, const float* __restrict__ wk,
                               const float* __restrict__ wv,
                               __half* __restrict__ x16, __half* __restrict__ W16)
{
    const int b = blockIdx.x;
    const int tid = threadIdx.x;
    const float* src;
    __half* dst;
    int i;
    if (b < 8192) {                 // x: 2097152 float4
        src = x; dst = x16; i = b * 256 + tid;
    } else {                        // weights: 262144 float4 each
        const int wb = b - 8192;
        const int w = wb >> 10;     // 0..2
        src = (w == 0) ? wq : (w == 1) ? wk : wv;
        dst = W16 + (long long)w * Dd * Dd;
        i = (wb & 1023) * 256 + tid;
    }
    const float4 v = reinterpret_cast<const float4*>(src)[i];
    __half2* o = reinterpret_cast<__half2*>(dst);
    o[2 * i]     = __floats2half2_rn(v.x, v.y);
    o[2 * i + 1] = __floats2half2_rn(v.z, v.w);
}

// ------- row softmax over S=2048: reads fp32 scores, writes fp16 P -------
__global__ void __launch_bounds__(256) softmax_kernel(const float* __restrict__ S32,
                                                      __half* __restrict__ P16)
{
    const float* row = S32 + (long long)blockIdx.x * Ss;
    __half* orow = P16 + (long long)blockIdx.x * Ss;
    const int tid = threadIdx.x;
    const int w = tid >> 5, l = tid & 31;

    float v[8];
    float m = -1e30f;
#pragma unroll
    for (int i = 0; i < 8; i++) { v[i] = row[tid + i * 256]; m = fmaxf(m, v[i]); }
#pragma unroll
    for (int o = 16; o > 0; o >>= 1) m = fmaxf(m, __shfl_xor_sync(0xFFFFFFFFu, m, o));

    __shared__ float smax[8], ssum[8];
    if (l == 0) smax[w] = m;
    __syncthreads();
    m = smax[0];
#pragma unroll
    for (int i = 1; i < 8; i++) m = fmaxf(m, smax[i]);

    float s = 0.0f;
#pragma unroll
    for (int i = 0; i < 8; i++) { v[i] = __expf(v[i] - m); s += v[i]; }
#pragma unroll
    for (int o = 16; o > 0; o >>= 1) s += __shfl_xor_sync(0xFFFFFFFFu, s, o);
    if (l == 0) ssum[w] = s;
    __syncthreads();
    float tot = 0.0f;
#pragma unroll
    for (int i = 0; i < 8; i++) tot += ssum[i];
    const float inv = 1.0f / tot;
#pragma unroll
    for (int i = 0; i < 8; i++) orow[tid + i * 256] = __float2half_rn(v[i] * inv);
}

// ---------------- host ----------------
extern "C" void kernel_launch(void* const* d_in, const int* in_sizes, int n_in,
                              void* d_out, int out_size)
{
    const float* x  = (const float*)d_in[0];
    const float* Wq = (const float*)d_in[1];
    const float* bq = (const float*)d_in[2];
    const float* Wk = (const float*)d_in[3];
    const float* bk = (const float*)d_in[4];
    const float* Wv = (const float*)d_in[5];
    const float* bv = (const float*)d_in[6];
    float* out = (float*)d_out;

    __half *x16, *W16, *Q16, *K16, *Vt16, *P16;
    float* P32;
    cudaGetSymbolAddress((void**)&x16, g_x16);
    cudaGetSymbolAddress((void**)&W16, g_W16);
    cudaGetSymbolAddress((void**)&Q16, g_Q16);
    cudaGetSymbolAddress((void**)&K16, g_K16);
    cudaGetSymbolAddress((void**)&Vt16, g_Vt16);
    cudaGetSymbolAddress((void**)&P32, g_P32);
    cudaGetSymbolAddress((void**)&P16, g_P16);

    cudaFuncSetAttribute((const void*)proj_kernel,
                         cudaFuncAttributeMaxDynamicSharedMemorySize, SMEM_BYTES);
    cudaFuncSetAttribute((const void*)bgemm_kernel,
                         cudaFuncAttributeMaxDynamicSharedMemorySize, SMEM_BYTES);

    // 0) one merged convert launch (x + 3 weights)
    cvt_all_kernel<<<8192 + 3072, 256>>>(x, Wq, Wk, Wv, x16, W16);

    const long long SD = (long long)Ss * Dd;
    const long long SS2 = (long long)Ss * Ss;

    // 1) merged Q/K/Vt projections: one 1536-CTA launch
    proj_kernel<<<1536, 256, SMEM_BYTES>>>(x16, W16, bq, bk, bv, Q16, K16, Vt16);

    // 2) scores = Q @ K^T / 32 -> fp32
    const dim3 g2(Ss / BN, Ss / BM, Bb);
    bgemm_kernel<<<g2, 256, SMEM_BYTES>>>(Q16, K16, P32, Ss, Dd, 0.03125f, SD, SD, SS2);

    // 3) softmax fp32 -> fp16 P
    softmax_kernel<<<Bb * Ss, 256>>>(P32, P16);

    // 4) out = P16 @ Vt16^T -> fp32
    const dim3 g3(Dd / BN, Ss / BM, Bb);
    bgemm_kernel<<<g3, 256, SMEM_BYTES>>>(P16, Vt16, out, Dd, Ss, 1.0f, SS2, SD, SD);
}